// round 1
// baseline (speedup 1.0000x reference)
#include <cuda_runtime.h>

// B_Splines: out[i][j] = spline(x[i]; coefs) * spline(t[j]; coefs_2)
// degree P=3, N_COEFS=128, knots[132] open-uniform on [0,1].
//
// Inputs (metadata order): x[8192], t[8192], knots[132], coefs[128], coefs_2[128]
// Output: float32 [8192, 8192]

#define NX 8192
#define NT 8192
#define PDEG 3
#define NCOEF 128
// interior spans: knots[3..128] are (i-3)/125 (fp32 linspace), spans k in [3,127]

__device__ float g_sx[NX];
__device__ float g_st[NT];

// ---------------------------------------------------------------------------
// Kernel 1: evaluate cubic B-spline at all x and t points (16384 points total).
// Only 4 basis functions are nonzero at any point; use the standard triangular
// basis algorithm within the knot span. Denominators within a valid span are
// strictly positive (span interval is nonempty), so no division guards needed.
// ---------------------------------------------------------------------------
__global__ void spline_eval_kernel(const float* __restrict__ x,
                                   const float* __restrict__ t,
                                   const float* __restrict__ knots,
                                   const float* __restrict__ coefs,
                                   const float* __restrict__ coefs2) {
    int i = blockIdx.x * blockDim.x + threadIdx.x;
    if (i >= NX + NT) return;

    const float* pts;
    const float* c;
    float* outv;
    int idx;
    if (i < NX) { pts = x; c = coefs;  outv = g_sx; idx = i; }
    else        { pts = t; c = coefs2; outv = g_st; idx = i - NX; }

    float xv = pts[idx];

    // Knot span: interior knots uniform -> initial guess, then robust local fix
    // against the actual fp32 knot values (handles linspace rounding).
    int k = 3 + (int)floorf(xv * 125.0f);
    if (k < 3) k = 3;
    if (k > 127) k = 127;
    while (k > 3   && xv <  __ldg(knots + k))     k--;
    while (k < 127 && xv >= __ldg(knots + k + 1)) k++;

    // Triangular basis computation (NURBS book A2.2) for the 4 nonzero fns.
    float left[PDEG + 1], right[PDEG + 1], N[PDEG + 1];
    N[0] = 1.0f;
#pragma unroll
    for (int j = 1; j <= PDEG; j++) {
        left[j]  = xv - __ldg(knots + (k + 1 - j));
        right[j] = __ldg(knots + (k + j)) - xv;
        float saved = 0.0f;
#pragma unroll
        for (int r = 0; r < j; r++) {
            float temp = N[r] / (right[r + 1] + left[j - r]);
            N[r] = saved + right[r + 1] * temp;
            saved = left[j - r] * temp;
        }
        N[j] = saved;
    }

    float s = 0.0f;
#pragma unroll
    for (int r = 0; r <= PDEG; r++)
        s += __ldg(c + (k - 3 + r)) * N[r];

    outv[idx] = s;
}

// ---------------------------------------------------------------------------
// Kernel 2: outer product, store-bandwidth bound.
// Each thread owns one float4 column group (st loaded once), loops 64 rows.
// Grid: (NT/1024 col tiles, NX/64 row tiles) = (8, 128) = 1024 CTAs.
// ---------------------------------------------------------------------------
#define TPB 256
#define ROWS_PER_BLOCK 64

__global__ __launch_bounds__(TPB) void outer_kernel(float* __restrict__ out) {
    int j = (blockIdx.x * TPB + threadIdx.x) * 4;          // column of the f4
    float4 s4 = *reinterpret_cast<const float4*>(g_st + j); // load once
    int r0 = blockIdx.y * ROWS_PER_BLOCK;

#pragma unroll 8
    for (int r = 0; r < ROWS_PER_BLOCK; r++) {
        float a = g_sx[r0 + r];                             // uniform broadcast
        float4 o;
        o.x = a * s4.x;
        o.y = a * s4.y;
        o.z = a * s4.z;
        o.w = a * s4.w;
        *reinterpret_cast<float4*>(out + (size_t)(r0 + r) * NT + j) = o;
    }
}

extern "C" void kernel_launch(void* const* d_in, const int* in_sizes, int n_in,
                              void* d_out, int out_size) {
    const float* x      = (const float*)d_in[0];
    const float* t      = (const float*)d_in[1];
    const float* knots  = (const float*)d_in[2];
    const float* coefs  = (const float*)d_in[3];
    const float* coefs2 = (const float*)d_in[4];
    float* out = (float*)d_out;

    spline_eval_kernel<<<(NX + NT + 255) / 256, 256>>>(x, t, knots, coefs, coefs2);

    dim3 grid(NT / (TPB * 4), NX / ROWS_PER_BLOCK);  // (8, 128)
    outer_kernel<<<grid, TPB>>>(out);
}

// round 2
// speedup vs baseline: 1.0221x; 1.0221x over previous
#include <cuda_runtime.h>

// B_Splines fused: out[i][j] = spline(x[i]; coefs) * spline(t[j]; coefs_2)
// degree P=3, N_COEFS=128, knots[132] open-uniform on [0,1].
//
// Single kernel: each CTA owns a 64-row x 1024-col tile of the 8192x8192
// output. Spline values are recomputed redundantly per CTA (cheap: 4 nonzero
// basis functions per point, fast divides on the idle MUFU pipe) so the whole
// problem is one DRAM-write-bound kernel with no serialized launches.
//
// Inputs (metadata order): x[8192], t[8192], knots[132], coefs[128], coefs_2[128]
// Output: float32 [8192, 8192]

#define NX 8192
#define NT 8192
#define PDEG 3

#define TPB 256
#define ROWS_PER_BLOCK 64
#define COLS_PER_BLOCK (TPB * 4)   // 1024

// Cubic B-spline evaluation at one point: find knot span (uniform interior
// knots give the initial guess; local search against the actual fp32 knot
// array fixes linspace rounding), then the triangular basis algorithm
// (NURBS book A2.2) over the 4 nonzero basis functions.
__device__ __forceinline__ float spline_eval(float xv,
                                             const float* __restrict__ knots,
                                             const float* __restrict__ c) {
    int k = 3 + (int)floorf(xv * 125.0f);
    k = max(3, min(127, k));
    while (k > 3   && xv <  __ldg(knots + k))     k--;
    while (k < 127 && xv >= __ldg(knots + k + 1)) k++;

    float left[PDEG + 1], right[PDEG + 1], N[PDEG + 1];
    N[0] = 1.0f;
#pragma unroll
    for (int j = 1; j <= PDEG; j++) {
        left[j]  = xv - __ldg(knots + (k + 1 - j));
        right[j] = __ldg(knots + (k + j)) - xv;
        float saved = 0.0f;
#pragma unroll
        for (int r = 0; r < j; r++) {
            float temp = __fdividef(N[r], right[r + 1] + left[j - r]);
            N[r] = saved + right[r + 1] * temp;
            saved = left[j - r] * temp;
        }
        N[j] = saved;
    }

    float s = 0.0f;
#pragma unroll
    for (int r = 0; r <= PDEG; r++)
        s += __ldg(c + (k - 3 + r)) * N[r];
    return s;
}

__global__ __launch_bounds__(TPB) void bspline_outer_fused(
    const float* __restrict__ x,
    const float* __restrict__ t,
    const float* __restrict__ knots,
    const float* __restrict__ coefs,
    const float* __restrict__ coefs2,
    float* __restrict__ out) {
    __shared__ float s_sx[ROWS_PER_BLOCK];

    const int tid = threadIdx.x;
    const int j   = blockIdx.x * COLS_PER_BLOCK + tid * 4;  // base column
    const int r0  = blockIdx.y * ROWS_PER_BLOCK;            // base row

    // Row spline values -> SMEM (threads 0..63), overlapped with column evals.
    if (tid < ROWS_PER_BLOCK) {
        float xv = __ldg(x + r0 + tid);
        s_sx[tid] = spline_eval(xv, knots, coefs);
    }

    // Column spline values for this thread's 4 columns (independent -> ILP).
    float4 tv = *reinterpret_cast<const float4*>(t + j);
    float4 s4;
    s4.x = spline_eval(tv.x, knots, coefs2);
    s4.y = spline_eval(tv.y, knots, coefs2);
    s4.z = spline_eval(tv.z, knots, coefs2);
    s4.w = spline_eval(tv.w, knots, coefs2);

    __syncthreads();

    // Store drain: 64 rows x 16B per thread, fully coalesced, streaming hint
    // (output is never re-read).
    float4* outp = reinterpret_cast<float4*>(out + (size_t)r0 * NT + j);
#pragma unroll 8
    for (int r = 0; r < ROWS_PER_BLOCK; r++) {
        float a = s_sx[r];
        float4 o;
        o.x = a * s4.x;
        o.y = a * s4.y;
        o.z = a * s4.z;
        o.w = a * s4.w;
        __stcs(outp, o);
        outp += NT / 4;
    }
}

extern "C" void kernel_launch(void* const* d_in, const int* in_sizes, int n_in,
                              void* d_out, int out_size) {
    const float* x      = (const float*)d_in[0];
    const float* t      = (const float*)d_in[1];
    const float* knots  = (const float*)d_in[2];
    const float* coefs  = (const float*)d_in[3];
    const float* coefs2 = (const float*)d_in[4];
    float* out = (float*)d_out;

    dim3 grid(NT / COLS_PER_BLOCK, NX / ROWS_PER_BLOCK);  // (8, 128)
    bspline_outer_fused<<<grid, TPB>>>(x, t, knots, coefs, coefs2, out);
}